// round 2
// baseline (speedup 1.0000x reference)
#include <cuda_runtime.h>
#include <cstdint>
#include <cstddef>

#define BATCH 4
#define SEQT  2048
#define CIN   1152
#define NE    1024
#define NH    16
#define HD    64
#define ROWS  (BATCH*SEQT)   // 8192

// ---- scratch (no allocations allowed) ----
__device__ float g_h[(size_t)ROWS * CIN];        // LN output, tf32-rounded
__device__ float g_qkv[(size_t)ROWS * 3 * NE];   // QKV, fp32
__device__ float g_y[(size_t)ROWS * NE];         // attention out, tf32-rounded

__device__ __forceinline__ uint32_t f2tf(float x) {
    uint32_t r; asm("cvt.rna.tf32.f32 %0, %1;" : "=r"(r) : "f"(x)); return r;
}
__device__ __forceinline__ float f2tff(float x) { return __uint_as_float(f2tf(x)); }

__device__ __forceinline__ void mma_tf32(float c[4], const uint32_t a[4], const uint32_t b[2]) {
    asm volatile(
        "mma.sync.aligned.m16n8k8.row.col.f32.tf32.tf32.f32 "
        "{%0,%1,%2,%3}, {%4,%5,%6,%7}, {%8,%9}, {%0,%1,%2,%3};\n"
        : "+f"(c[0]), "+f"(c[1]), "+f"(c[2]), "+f"(c[3])
        : "r"(a[0]), "r"(a[1]), "r"(a[2]), "r"(a[3]), "r"(b[0]), "r"(b[1]));
}

// ------------------------- LayerNorm -------------------------
__global__ void ln_kernel(const float* __restrict__ x, const float* __restrict__ w,
                          const float* __restrict__ bb, float* __restrict__ h) {
    int row = blockIdx.x;
    const float* xr = x + (size_t)row * CIN;
    float s1 = 0.f, s2 = 0.f;
    for (int i = threadIdx.x; i < CIN; i += 256) { float v = xr[i]; s1 += v; s2 += v * v; }
    #pragma unroll
    for (int o = 16; o; o >>= 1) {
        s1 += __shfl_xor_sync(0xffffffffu, s1, o);
        s2 += __shfl_xor_sync(0xffffffffu, s2, o);
    }
    __shared__ float sh1[8], sh2[8];
    int wid = threadIdx.x >> 5, lane = threadIdx.x & 31;
    if (lane == 0) { sh1[wid] = s1; sh2[wid] = s2; }
    __syncthreads();
    float S1 = 0.f, S2 = 0.f;
    #pragma unroll
    for (int i = 0; i < 8; i++) { S1 += sh1[i]; S2 += sh2[i]; }
    float mean = S1 * (1.f / CIN);
    float var  = S2 * (1.f / CIN) - mean * mean;
    float inv  = rsqrtf(var + 1e-5f);
    float* hr = h + (size_t)row * CIN;
    for (int i = threadIdx.x; i < CIN; i += 256)
        hr[i] = f2tff((xr[i] - mean) * inv * w[i] + bb[i]);
}

// ------------------------- TF32 GEMM: C = A@B + bias -------------------------
// A [M,K] row-major (pre-rounded tf32), B [K,N] row-major (rounded at smem store)
__global__ __launch_bounds__(256) void gemm_tf32(
        const float* __restrict__ A, const float* __restrict__ Bm,
        const float* __restrict__ bias, float* __restrict__ C,
        int M, int N, int K) {
    __shared__ float As[128][20];
    __shared__ float Bs[16][136];
    int tid = threadIdx.x;
    int lane = tid & 31, wid = tid >> 5;
    int wm = (wid & 3) * 32, wn = (wid >> 2) * 64;
    int bm = blockIdx.y * 128, bn = blockIdx.x * 128;
    int g = lane >> 2, tg = lane & 3;

    float acc[2][8][4];
    #pragma unroll
    for (int mt = 0; mt < 2; mt++)
        #pragma unroll
        for (int nt = 0; nt < 8; nt++)
            #pragma unroll
            for (int i = 0; i < 4; i++) acc[mt][nt][i] = 0.f;

    for (int k0 = 0; k0 < K; k0 += 16) {
        #pragma unroll
        for (int i = 0; i < 2; i++) {
            int f = tid + i * 256;           // 0..511
            int r = f >> 2, c = (f & 3) * 4;
            float4 v = *reinterpret_cast<const float4*>(A + (size_t)(bm + r) * K + k0 + c);
            As[r][c + 0] = v.x; As[r][c + 1] = v.y; As[r][c + 2] = v.z; As[r][c + 3] = v.w;
        }
        #pragma unroll
        for (int i = 0; i < 2; i++) {
            int f = tid + i * 256;
            int r = f >> 5, c = (f & 31) * 4;
            float4 v = *reinterpret_cast<const float4*>(Bm + (size_t)(k0 + r) * N + bn + c);
            Bs[r][c + 0] = f2tff(v.x); Bs[r][c + 1] = f2tff(v.y);
            Bs[r][c + 2] = f2tff(v.z); Bs[r][c + 3] = f2tff(v.w);
        }
        __syncthreads();
        #pragma unroll
        for (int ks = 0; ks < 2; ks++) {
            uint32_t a[2][4], b[8][2];
            #pragma unroll
            for (int mt = 0; mt < 2; mt++) {
                int r = wm + mt * 16 + g, c = ks * 8 + tg;
                a[mt][0] = __float_as_uint(As[r][c]);
                a[mt][1] = __float_as_uint(As[r + 8][c]);
                a[mt][2] = __float_as_uint(As[r][c + 4]);
                a[mt][3] = __float_as_uint(As[r + 8][c + 4]);
            }
            #pragma unroll
            for (int nt = 0; nt < 8; nt++) {
                int c = wn + nt * 8 + g, r = ks * 8 + tg;
                b[nt][0] = __float_as_uint(Bs[r][c]);
                b[nt][1] = __float_as_uint(Bs[r + 4][c]);
            }
            #pragma unroll
            for (int mt = 0; mt < 2; mt++)
                #pragma unroll
                for (int nt = 0; nt < 8; nt++)
                    mma_tf32(acc[mt][nt], a[mt], b[nt]);
        }
        __syncthreads();
    }
    #pragma unroll
    for (int mt = 0; mt < 2; mt++) {
        int r0 = bm + wm + mt * 16 + g;
        #pragma unroll
        for (int nt = 0; nt < 8; nt++) {
            int c0 = bn + wn + nt * 8 + tg * 2;
            float bz0 = bias[c0], bz1 = bias[c0 + 1];
            C[(size_t)r0 * N + c0]       = acc[mt][nt][0] + bz0;
            C[(size_t)r0 * N + c0 + 1]   = acc[mt][nt][1] + bz1;
            C[(size_t)(r0 + 8) * N + c0]     = acc[mt][nt][2] + bz0;
            C[(size_t)(r0 + 8) * N + c0 + 1] = acc[mt][nt][3] + bz1;
        }
    }
}

// ------------------------- Flash attention (causal) -------------------------
// Block = (q-tile 64 rows, head, batch). 4 warps x 16 q-rows. TF32 mma for
// S = Q K^T and O += P V; online softmax in fp32. P reuses the K smem buffer.
__global__ __launch_bounds__(128) void attn_kernel(const float* __restrict__ qkv,
                                                   float* __restrict__ y) {
    __shared__ float bufK[64][68];  // K tile; reused for P
    __shared__ float bufV[64][68];
    int qt = blockIdx.x, h = blockIdx.y, b = blockIdx.z;
    int tid = threadIdx.x, lane = tid & 31, w = tid >> 5;
    int g = lane >> 2, tg = lane & 3;
    int q0 = qt * 64;
    const size_t rstr = (size_t)3 * NE;
    const float* qbase = qkv + ((size_t)b * SEQT + q0) * rstr + h * HD;
    const float* kbase = qkv + ((size_t)b * SEQT) * rstr + NE + h * HD;
    const float* vbase = qkv + ((size_t)b * SEQT) * rstr + 2 * NE + h * HD;

    const float scale = 0.125f;  // 1/sqrt(64), folded into Q
    #pragma unroll
    for (int i = 0; i < 8; i++) {
        int idx = tid + i * 128;            // 0..1023
        int r = idx >> 4, c = (idx & 15) * 4;
        float4 v = *reinterpret_cast<const float4*>(qbase + (size_t)r * rstr + c);
        bufK[r][c + 0] = f2tff(v.x * scale); bufK[r][c + 1] = f2tff(v.y * scale);
        bufK[r][c + 2] = f2tff(v.z * scale); bufK[r][c + 3] = f2tff(v.w * scale);
    }
    __syncthreads();
    uint32_t qf[8][4];
    #pragma unroll
    for (int ks = 0; ks < 8; ks++) {
        int r = w * 16 + g, c = ks * 8 + tg;
        qf[ks][0] = __float_as_uint(bufK[r][c]);
        qf[ks][1] = __float_as_uint(bufK[r + 8][c]);
        qf[ks][2] = __float_as_uint(bufK[r][c + 4]);
        qf[ks][3] = __float_as_uint(bufK[r + 8][c + 4]);
    }
    __syncthreads();

    float O[8][4];
    #pragma unroll
    for (int dt = 0; dt < 8; dt++)
        #pragma unroll
        for (int i = 0; i < 4; i++) O[dt][i] = 0.f;
    float m0 = -1e30f, m1 = -1e30f, l0 = 0.f, l1 = 0.f;

    for (int kt = 0; kt <= qt; kt++) {
        int kb = kt * 64;
        #pragma unroll
        for (int i = 0; i < 8; i++) {
            int idx = tid + i * 128;
            int r = idx >> 4, c = (idx & 15) * 4;
            float4 kv4 = *reinterpret_cast<const float4*>(kbase + (size_t)(kb + r) * rstr + c);
            bufK[r][c + 0] = f2tff(kv4.x); bufK[r][c + 1] = f2tff(kv4.y);
            bufK[r][c + 2] = f2tff(kv4.z); bufK[r][c + 3] = f2tff(kv4.w);
            float4 vv4 = *reinterpret_cast<const float4*>(vbase + (size_t)(kb + r) * rstr + c);
            bufV[r][c + 0] = f2tff(vv4.x); bufV[r][c + 1] = f2tff(vv4.y);
            bufV[r][c + 2] = f2tff(vv4.z); bufV[r][c + 3] = f2tff(vv4.w);
        }
        __syncthreads();

        float S[8][4];
        #pragma unroll
        for (int nt = 0; nt < 8; nt++)
            #pragma unroll
            for (int i = 0; i < 4; i++) S[nt][i] = 0.f;
        #pragma unroll
        for (int ks = 0; ks < 8; ks++) {
            uint32_t bk[8][2];
            #pragma unroll
            for (int nt = 0; nt < 8; nt++) {
                bk[nt][0] = __float_as_uint(bufK[nt * 8 + g][ks * 8 + tg]);
                bk[nt][1] = __float_as_uint(bufK[nt * 8 + g][ks * 8 + tg + 4]);
            }
            #pragma unroll
            for (int nt = 0; nt < 8; nt++) mma_tf32(S[nt], qf[ks], bk[nt]);
        }

        if (kt == qt) {  // diagonal tile: causal mask
            int r = q0 + w * 16 + g;
            #pragma unroll
            for (int nt = 0; nt < 8; nt++) {
                int c = kb + nt * 8 + tg * 2;
                if (c     > r)     S[nt][0] = -1e30f;
                if (c + 1 > r)     S[nt][1] = -1e30f;
                if (c     > r + 8) S[nt][2] = -1e30f;
                if (c + 1 > r + 8) S[nt][3] = -1e30f;
            }
        }

        float mx0 = -1e30f, mx1 = -1e30f;
        #pragma unroll
        for (int nt = 0; nt < 8; nt++) {
            mx0 = fmaxf(mx0, fmaxf(S[nt][0], S[nt][1]));
            mx1 = fmaxf(mx1, fmaxf(S[nt][2], S[nt][3]));
        }
        #pragma unroll
        for (int o = 1; o <= 2; o <<= 1) {
            mx0 = fmaxf(mx0, __shfl_xor_sync(0xffffffffu, mx0, o));
            mx1 = fmaxf(mx1, __shfl_xor_sync(0xffffffffu, mx1, o));
        }
        float nm0 = fmaxf(m0, mx0), nm1 = fmaxf(m1, mx1);
        float al0 = __expf(m0 - nm0), al1 = __expf(m1 - nm1);
        float rs0 = 0.f, rs1 = 0.f;
        #pragma unroll
        for (int nt = 0; nt < 8; nt++) {
            S[nt][0] = __expf(S[nt][0] - nm0); rs0 += S[nt][0];
            S[nt][1] = __expf(S[nt][1] - nm0); rs0 += S[nt][1];
            S[nt][2] = __expf(S[nt][2] - nm1); rs1 += S[nt][2];
            S[nt][3] = __expf(S[nt][3] - nm1); rs1 += S[nt][3];
        }
        #pragma unroll
        for (int o = 1; o <= 2; o <<= 1) {
            rs0 += __shfl_xor_sync(0xffffffffu, rs0, o);
            rs1 += __shfl_xor_sync(0xffffffffu, rs1, o);
        }
        l0 = l0 * al0 + rs0; l1 = l1 * al1 + rs1;
        m0 = nm0; m1 = nm1;
        #pragma unroll
        for (int dt = 0; dt < 8; dt++) {
            O[dt][0] *= al0; O[dt][1] *= al0; O[dt][2] *= al1; O[dt][3] *= al1;
        }

        __syncthreads();  // all warps done reading K before P overwrites it
        #pragma unroll
        for (int nt = 0; nt < 8; nt++) {
            int r = w * 16 + g, c = nt * 8 + tg * 2;
            bufK[r][c]         = f2tff(S[nt][0]);
            bufK[r][c + 1]     = f2tff(S[nt][1]);
            bufK[r + 8][c]     = f2tff(S[nt][2]);
            bufK[r + 8][c + 1] = f2tff(S[nt][3]);
        }
        __syncwarp();  // each warp reads back only its own 16 P-rows

        #pragma unroll
        for (int ks = 0; ks < 8; ks++) {
            uint32_t pa[4];
            int r = w * 16 + g, c = ks * 8 + tg;
            pa[0] = __float_as_uint(bufK[r][c]);
            pa[1] = __float_as_uint(bufK[r + 8][c]);
            pa[2] = __float_as_uint(bufK[r][c + 4]);
            pa[3] = __float_as_uint(bufK[r + 8][c + 4]);
            #pragma unroll
            for (int dt = 0; dt < 8; dt++) {
                uint32_t bv[2];
                bv[0] = __float_as_uint(bufV[ks * 8 + tg][dt * 8 + g]);
                bv[1] = __float_as_uint(bufV[ks * 8 + tg + 4][dt * 8 + g]);
                mma_tf32(O[dt], pa, bv);
            }
        }
        __syncthreads();  // before next tile overwrites K/V buffers
    }

    float il0 = 1.f / l0, il1 = 1.f / l1;
    int r = q0 + w * 16 + g;
    float* yb  = y + ((size_t)b * SEQT + r) * NE + h * HD;
    float* yb8 = y + ((size_t)b * SEQT + r + 8) * NE + h * HD;
    #pragma unroll
    for (int dt = 0; dt < 8; dt++) {
        int c = dt * 8 + tg * 2;
        yb[c]      = f2tff(O[dt][0] * il0);
        yb[c + 1]  = f2tff(O[dt][1] * il0);
        yb8[c]     = f2tff(O[dt][2] * il1);
        yb8[c + 1] = f2tff(O[dt][3] * il1);
    }
}

// ------------------------- launch -------------------------
extern "C" void kernel_launch(void* const* d_in, const int* in_sizes, int n_in,
                              void* d_out, int out_size) {
    const float* x      = (const float*)d_in[0];
    const float* ln_w   = (const float*)d_in[1];
    const float* ln_b   = (const float*)d_in[2];
    const float* W_attn = (const float*)d_in[3];
    const float* b_attn = (const float*)d_in[4];
    const float* W_proj = (const float*)d_in[5];
    const float* b_proj = (const float*)d_in[6];
    float* out = (float*)d_out;

    float *h, *qkv, *y;
    cudaGetSymbolAddress((void**)&h,   g_h);
    cudaGetSymbolAddress((void**)&qkv, g_qkv);
    cudaGetSymbolAddress((void**)&y,   g_y);

    ln_kernel<<<ROWS, 256>>>(x, ln_w, ln_b, h);
    gemm_tf32<<<dim3(3 * NE / 128, ROWS / 128), 256>>>(h, W_attn, b_attn, qkv, ROWS, 3 * NE, CIN);
    attn_kernel<<<dim3(SEQT / 64, NH, BATCH), 128>>>(qkv, y);
    gemm_tf32<<<dim3(NE / 128, ROWS / 128), 256>>>(y, W_proj, b_proj, out, ROWS, NE, NE);
}